// round 1
// baseline (speedup 1.0000x reference)
#include <cuda_runtime.h>
#include <cuda_bf16.h>
#include <cstdint>

// Real spherical harmonics up to L=20 -> 441 columns per point.
// Output [N, 441] fp32 (882 MB for N=500k) => HBM-store-bound (~110us floor).
//
// Strategy:
//  - 64 points per CTA, 64 threads (1 point/thread).
//  - Each thread runs the exact fp32 recurrences of the reference, scatter-
//    writing its 441 values into a shared tile (stride 441 words across the
//    warp => 441 odd => conflict-free banks).
//  - Block then flat-copies the tile to global with float4 (fully coalesced,
//    tile byte size 112896 = blockIdx stride, 16B aligned).
//  - 2 CTAs/SM (2 x 112896B smem) so compute of one CTA overlaps copy of the
//    other.
//  - All coefficients ((2l-1)/(l-m), -(l+m-1)/(l-m), norm*[sqrt2]) are built
//    at compile time (constexpr, incl. constexpr Newton sqrt) into one
//    __constant__ float4 table.

#define SH_L 20
#define SH_K 441            // (L+1)^2
#define SH_PAIRS 231        // number of (l,m) pairs, m=0..L, l=m..L
#define TILE 64
#define THREADS 64
#define SMEM_BYTES (TILE * SH_K * 4)

// ---------------- compile-time tables ----------------
constexpr double kPI = 3.141592653589793238462643383279502884;

constexpr double csqrt(double x) {
    double g = (x > 1.0) ? x : 1.0;
    for (int i = 0; i < 200; ++i) g = 0.5 * (g + x / g);
    return g;
}

struct SHTables {
    // iteration order: m = 0..L, l = m..L  (index ci)
    // x = A  = (2l-1)/(l-m)        (valid for l >= m+2, else 0)
    // y = B  = -(l+m-1)/(l-m)      (valid for l >= m+2, else 0)
    // z = NF = norm(l,m) * (m>0 ? sqrt2 : 1)
    float4 C[SH_PAIRS];
};

constexpr SHTables make_tables() {
    SHTables t{};
    const double sqrt2 = csqrt(2.0);
    int ci = 0;
    for (int m = 0; m <= SH_L; ++m) {
        for (int l = m; l <= SH_L; ++l) {
            // ratio = (l-m)! / (l+m)! = 1 / prod_{k=l-m+1}^{l+m} k
            double prod = 1.0;
            for (int k = l - m + 1; k <= l + m; ++k) prod *= (double)k;
            double norm = csqrt((2.0 * l + 1.0) / (4.0 * kPI) / prod);
            double nf = (m > 0) ? norm * sqrt2 : norm;
            double A = 0.0, B = 0.0;
            if (l >= m + 2) {
                A = (double)(2 * l - 1) / (double)(l - m);
                B = -(double)(l + m - 1) / (double)(l - m);
            }
            t.C[ci].x = (float)A;
            t.C[ci].y = (float)B;
            t.C[ci].z = (float)nf;
            t.C[ci].w = 0.0f;
            ++ci;
        }
    }
    return t;
}

__constant__ SHTables cTab = make_tables();

// ---------------- kernel ----------------
__global__ void __launch_bounds__(THREADS, 2)
sph_harm_kernel(const float* __restrict__ coords, float* __restrict__ out, int n)
{
    extern __shared__ float sh[];   // TILE * SH_K floats
    const int base = blockIdx.x * TILE;
    const int t = threadIdx.x;
    const int p = base + t;

    if (p < n) {
        const float x = coords[3 * p + 0];
        const float y = coords[3 * p + 1];
        const float z = coords[3 * p + 2];

        const float r  = sqrtf(x * x + y * y + z * z);
        float ct = z / r;
        ct = fminf(1.0f, fmaxf(-1.0f, ct));
        const float st = sqrtf(fmaxf(1.0f - ct * ct, 0.0f));

        // cos(azim), sin(azim) without atan2
        const float rho2 = x * x + y * y;
        float c1, s1;
        if (rho2 > 0.0f) {
            const float ir = rsqrtf(rho2);
            c1 = x * ir;
            s1 = y * ir;
        } else {
            c1 = 1.0f;   // atan2(0,0) = 0
            s1 = 0.0f;
        }

        float* row = sh + t * SH_K;

        float pmm = 1.0f;           // P_m^m
        float cm = 1.0f, sm = 0.0f; // cos(m*azim), sin(m*azim)
        int ci = 0;

        #pragma unroll
        for (int m = 0; m <= SH_L; ++m) {
            if (m > 0) {
                pmm = pmm * (-(2.0f * (float)m - 1.0f)) * st;
                const float cn = cm * c1 - sm * s1;
                const float sn = sm * c1 + cm * s1;
                cm = cn; sm = sn;
            }

            // l = m
            float p2 = pmm;
            {
                const float nf = cTab.C[ci].z;
                if (m == 0) {
                    row[m * (m + 1)] = nf * p2;
                } else {
                    const float b = nf * p2;
                    row[m * (m + 1) + m] = b * cm;
                    row[m * (m + 1) - m] = b * sm;
                }
                ++ci;
            }

            if (m < SH_L) {
                // l = m + 1
                float p1 = (2.0f * (float)m + 1.0f) * ct * pmm;
                {
                    const int l = m + 1;
                    const float nf = cTab.C[ci].z;
                    if (m == 0) {
                        row[l * (l + 1)] = nf * p1;
                    } else {
                        const float b = nf * p1;
                        row[l * (l + 1) + m] = b * cm;
                        row[l * (l + 1) - m] = b * sm;
                    }
                    ++ci;
                }
                #pragma unroll
                for (int l = m + 2; l <= SH_L; ++l) {
                    const float4 c = cTab.C[ci];
                    const float u = c.x * ct;        // A*ct (off critical chain)
                    const float v = c.y * p2;        // B*P_{l-2}
                    const float pv = fmaf(u, p1, v); // P_l
                    const float nf = c.z;
                    if (m == 0) {
                        row[l * (l + 1)] = nf * pv;
                    } else {
                        const float b = nf * pv;
                        row[l * (l + 1) + m] = b * cm;
                        row[l * (l + 1) - m] = b * sm;
                    }
                    p2 = p1; p1 = pv;
                    ++ci;
                }
            }
        }
    }

    __syncthreads();

    // coalesced tile -> global copy
    const int npts = min(TILE, n - base);
    if (npts <= 0) return;
    const int total = npts * SH_K;          // floats in this tile
    float* gbase = out + (size_t)base * SH_K;

    const int n4 = total >> 2;              // total is divisible by 4 when npts%4==0
    const float4* s4 = reinterpret_cast<const float4*>(sh);
    float4* o4 = reinterpret_cast<float4*>(gbase);
    for (int i = t; i < n4; i += THREADS) {
        o4[i] = s4[i];
    }
    for (int i = (n4 << 2) + t; i < total; i += THREADS) {
        gbase[i] = sh[i];
    }
}

extern "C" void kernel_launch(void* const* d_in, const int* in_sizes, int n_in,
                              void* d_out, int out_size) {
    const float* coords = (const float*)d_in[0];
    float* out = (float*)d_out;
    const int n = in_sizes[0] / 3;

    cudaFuncSetAttribute(sph_harm_kernel,
                         cudaFuncAttributeMaxDynamicSharedMemorySize, SMEM_BYTES);

    const int blocks = (n + TILE - 1) / TILE;
    sph_harm_kernel<<<blocks, THREADS, SMEM_BYTES>>>(coords, out, n);
}

// round 2
// speedup vs baseline: 1.9889x; 1.9889x over previous
#include <cuda_runtime.h>
#include <cuda_bf16.h>
#include <cstdint>

// Real spherical harmonics up to L=20 -> 441 cols/point, N=500k, fp32 out.
// 882 MB of output => HBM-write-bound, ~110us floor at 8 TB/s.
//
// Round-2 design:
//  - TILE=32 points/CTA, 128 threads: 4 threads per point, split by m mod 4.
//    Warp w handles m = w, w+4, w+8, ... for all 32 points (lane = point).
//    P_m^m advanced 4 m-steps at a time (constant * st^4), cos/sin(m phi)
//    advanced by angle-addition with (cos 4phi, sin 4phi).
//  - All recurrence coefficients + norms are compile-time constants produced
//    by constexpr template recursion -> FFMA/FMUL immediates. Zero LDC.
//  - smem tile 32*441*4 = 56448 B -> 4 CTAs/SM = 16 warps/SM (4/SMSP).
//  - Scatter STS (stride 441 words, odd => conflict-free), then coalesced
//    float4 tile->GMEM copy. 4 CTAs/SM overlap compute and copy phases.

#define SH_L 20
#define SH_K 441
#define TILE 32
#define THREADS 128
#define SMEM_BYTES (TILE * SH_K * 4)

// ---------- compile-time math ----------
__host__ __device__ constexpr double kPI_c() { return 3.141592653589793238462643383279502884; }

__host__ __device__ constexpr double csqrt(double x) {
    double g = (x > 1.0) ? x : 1.0;
    for (int i = 0; i < 200; ++i) g = 0.5 * (g + x / g);
    return g;
}

// (l-m)!/(l+m)! = 1 / prod_{k=l-m+1}^{l+m} k
__host__ __device__ constexpr double inv_ratio(int l, int m) {
    double p = 1.0;
    for (int k = l - m + 1; k <= l + m; ++k) p *= (double)k;
    return p;
}

// norm(l,m) * (m>0 ? sqrt2 : 1)
template <int L_, int M>
__host__ __device__ constexpr float nf_val() {
    double norm = csqrt((2.0 * L_ + 1.0) / (4.0 * kPI_c()) / inv_ratio(L_, M));
    return (float)(M > 0 ? norm * csqrt(2.0) : norm);
}

// ---------- store helpers ----------
template <int M, int L_>
__device__ __forceinline__ void storepair(float* __restrict__ row, float b,
                                          float cm, float sm) {
    if constexpr (M == 0) {
        row[L_ * (L_ + 1)] = b;
    } else {
        row[L_ * (L_ + 1) + M] = b * cm;
        row[L_ * (L_ + 1) - M] = b * sm;
    }
}

// ---------- l recursion for fixed m: l = L_ .. SH_L ----------
template <int M, int L_>
__device__ __forceinline__ void lstep(float* __restrict__ row, float ct,
                                      float cm, float sm, float p1, float p2) {
    constexpr float A = (float)((double)(2 * L_ - 1) / (double)(L_ - M));
    constexpr float B = (float)(-(double)(L_ + M - 1) / (double)(L_ - M));
    const float pv = fmaf(A * ct, p1, B * p2);
    constexpr float NF = nf_val<L_, M>();
    storepair<M, L_>(row, NF * pv, cm, sm);
    if constexpr (L_ < SH_L) lstep<M, L_ + 1>(row, ct, cm, sm, pv, p1);
}

// ---------- m chain: this warp's residue, stepping m += 4 ----------
template <int M>
__device__ __forceinline__ void mchain(float* __restrict__ row, float ct,
                                       float st4, float c4, float s4,
                                       float pmm, float cm, float sm) {
    // l = M
    constexpr float NF0 = nf_val<M, M>();
    storepair<M, M>(row, NF0 * pmm, cm, sm);
    if constexpr (M < SH_L) {
        // l = M+1
        constexpr float C1 = (float)(2 * M + 1);
        const float p1 = (C1 * ct) * pmm;
        constexpr float NF1 = nf_val<M + 1, M>();
        storepair<M, M + 1>(row, NF1 * p1, cm, sm);
        if constexpr (M + 2 <= SH_L) lstep<M, M + 2>(row, ct, cm, sm, p1, pmm);
    }
    if constexpr (M + 4 <= SH_L) {
        // P_{m+4}^{m+4} = (2m+1)(2m+3)(2m+5)(2m+7) * st^4 * P_m^m
        constexpr float F = (float)((double)(2 * M + 1) * (2 * M + 3) *
                                    (2 * M + 5) * (2 * M + 7));
        const float pmm2 = (pmm * F) * st4;
        const float cn = fmaf(cm, c4, -(sm * s4));
        const float sn = fmaf(sm, c4, cm * s4);
        mchain<M + 4>(row, ct, st4, c4, s4, pmm2, cn, sn);
    }
}

// ---------- kernel ----------
__global__ void __launch_bounds__(THREADS, 4)
sph_harm_kernel(const float* __restrict__ coords, float* __restrict__ out, int n)
{
    extern __shared__ float sh[];           // TILE * SH_K floats
    const int base = blockIdx.x * TILE;
    const int t = threadIdx.x;
    const int lane = t & 31;                // point within tile
    const int w = t >> 5;                   // m residue (0..3)
    const int p = base + lane;

    if (p < n) {
        const float x = coords[3 * p + 0];
        const float y = coords[3 * p + 1];
        const float z = coords[3 * p + 2];

        const float r = sqrtf(x * x + y * y + z * z);
        float ct = z / r;
        ct = fminf(1.0f, fmaxf(-1.0f, ct));
        const float st = sqrtf(fmaxf(1.0f - ct * ct, 0.0f));
        const float st2 = st * st;
        const float st4 = st2 * st2;

        const float rho2 = x * x + y * y;
        float c1, s1;
        if (rho2 > 0.0f) {
            const float ir = rsqrtf(rho2);
            c1 = x * ir;
            s1 = y * ir;
        } else {
            c1 = 1.0f;
            s1 = 0.0f;
        }
        // double/triple/quad angle
        const float c2 = fmaf(c1, c1, -(s1 * s1));
        const float s2 = 2.0f * c1 * s1;
        const float c3 = fmaf(c2, c1, -(s2 * s1));
        const float s3 = fmaf(s2, c1, c2 * s1);
        const float c4 = fmaf(c2, c2, -(s2 * s2));
        const float s4 = 2.0f * c2 * s2;

        float* row = sh + lane * SH_K;

        if (w == 0) {
            mchain<0>(row, ct, st4, c4, s4, 1.0f, 1.0f, 0.0f);
        } else if (w == 1) {
            mchain<1>(row, ct, st4, c4, s4, -st, c1, s1);
        } else if (w == 2) {
            const float pmm = (3.0f * st) * st;                 // P_2^2
            mchain<2>(row, ct, st4, c4, s4, pmm, c2, s2);
        } else {
            const float pmm = ((-15.0f * st) * st) * st;        // P_3^3
            mchain<3>(row, ct, st4, c4, s4, pmm, c3, s3);
        }
    }

    __syncthreads();

    // coalesced tile -> global copy
    const int npts = min(TILE, n - base);
    if (npts <= 0) return;
    const int total = npts * SH_K;
    float* gbase = out + (size_t)base * SH_K;

    const int n4 = total >> 2;
    const float4* s4v = reinterpret_cast<const float4*>(sh);
    float4* o4 = reinterpret_cast<float4*>(gbase);
    #pragma unroll 4
    for (int i = t; i < n4; i += THREADS) {
        o4[i] = s4v[i];
    }
    for (int i = (n4 << 2) + t; i < total; i += THREADS) {
        gbase[i] = sh[i];
    }
}

extern "C" void kernel_launch(void* const* d_in, const int* in_sizes, int n_in,
                              void* d_out, int out_size) {
    const float* coords = (const float*)d_in[0];
    float* out = (float*)d_out;
    const int n = in_sizes[0] / 3;

    cudaFuncSetAttribute(sph_harm_kernel,
                         cudaFuncAttributeMaxDynamicSharedMemorySize, SMEM_BYTES);
    cudaFuncSetAttribute(sph_harm_kernel,
                         cudaFuncAttributePreferredSharedMemoryCarveout, 100);

    const int blocks = (n + TILE - 1) / TILE;
    sph_harm_kernel<<<blocks, THREADS, SMEM_BYTES>>>(coords, out, n);
}

// round 3
// speedup vs baseline: 1.9965x; 1.0038x over previous
#include <cuda_runtime.h>
#include <cuda_bf16.h>
#include <cstdint>

// Real spherical harmonics up to L=20 -> 441 cols/point, N=500k, fp32 out.
// 882 MB of output => HBM-write-bound, ~110us floor at 8 TB/s.
//
// Round-3 design (changes vs round 2 marked *):
//  - TILE=32 points/CTA, 128 threads: 4 threads per point, split by m mod 4.
//  - All recurrence coefficients + norms are compile-time immediates.
//  - smem tile 32*441*4 = 56448 B -> 4 CTAs/SM = 16 warps/SM.
//  - Scatter STS (stride 441 words, odd => conflict-free).
//  * Tile -> GMEM via ONE 1D bulk TMA store (cp.async.bulk) instead of the
//    LDS.128/STG.128 copy loop: removes ~78us of chip-wide STG issue cost
//    and all LDS traffic. fence.proxy.async orders STS before the TMA read.

#define SH_L 20
#define SH_K 441
#define TILE 32
#define THREADS 128
#define SMEM_BYTES (TILE * SH_K * 4)

// ---------- compile-time math ----------
__host__ __device__ constexpr double kPI_c() { return 3.141592653589793238462643383279502884; }

__host__ __device__ constexpr double csqrt(double x) {
    double g = (x > 1.0) ? x : 1.0;
    for (int i = 0; i < 200; ++i) g = 0.5 * (g + x / g);
    return g;
}

__host__ __device__ constexpr double inv_ratio(int l, int m) {
    double p = 1.0;
    for (int k = l - m + 1; k <= l + m; ++k) p *= (double)k;
    return p;
}

template <int L_, int M>
__host__ __device__ constexpr float nf_val() {
    double norm = csqrt((2.0 * L_ + 1.0) / (4.0 * kPI_c()) / inv_ratio(L_, M));
    return (float)(M > 0 ? norm * csqrt(2.0) : norm);
}

// ---------- store helpers ----------
template <int M, int L_>
__device__ __forceinline__ void storepair(float* __restrict__ row, float b,
                                          float cm, float sm) {
    if constexpr (M == 0) {
        row[L_ * (L_ + 1)] = b;
    } else {
        row[L_ * (L_ + 1) + M] = b * cm;
        row[L_ * (L_ + 1) - M] = b * sm;
    }
}

// ---------- l recursion for fixed m ----------
template <int M, int L_>
__device__ __forceinline__ void lstep(float* __restrict__ row, float ct,
                                      float cm, float sm, float p1, float p2) {
    constexpr float A = (float)((double)(2 * L_ - 1) / (double)(L_ - M));
    constexpr float B = (float)(-(double)(L_ + M - 1) / (double)(L_ - M));
    const float pv = fmaf(A * ct, p1, B * p2);
    constexpr float NF = nf_val<L_, M>();
    storepair<M, L_>(row, NF * pv, cm, sm);
    if constexpr (L_ < SH_L) lstep<M, L_ + 1>(row, ct, cm, sm, pv, p1);
}

// ---------- m chain: one residue class, m += 4 ----------
template <int M>
__device__ __forceinline__ void mchain(float* __restrict__ row, float ct,
                                       float st4, float c4, float s4,
                                       float pmm, float cm, float sm) {
    constexpr float NF0 = nf_val<M, M>();
    storepair<M, M>(row, NF0 * pmm, cm, sm);
    if constexpr (M < SH_L) {
        constexpr float C1 = (float)(2 * M + 1);
        const float p1 = (C1 * ct) * pmm;
        constexpr float NF1 = nf_val<M + 1, M>();
        storepair<M, M + 1>(row, NF1 * p1, cm, sm);
        if constexpr (M + 2 <= SH_L) lstep<M, M + 2>(row, ct, cm, sm, p1, pmm);
    }
    if constexpr (M + 4 <= SH_L) {
        constexpr float F = (float)((double)(2 * M + 1) * (2 * M + 3) *
                                    (2 * M + 5) * (2 * M + 7));
        const float pmm2 = (pmm * F) * st4;
        const float cn = fmaf(cm, c4, -(sm * s4));
        const float sn = fmaf(sm, c4, cm * s4);
        mchain<M + 4>(row, ct, st4, c4, s4, pmm2, cn, sn);
    }
}

__device__ __forceinline__ uint32_t smem_u32(const void* p) {
    uint32_t a;
    asm("{ .reg .u64 t; cvta.to.shared.u64 t, %1; cvt.u32.u64 %0, t; }"
        : "=r"(a) : "l"(p));
    return a;
}

// ---------- kernel ----------
__global__ void __launch_bounds__(THREADS, 4)
sph_harm_kernel(const float* __restrict__ coords, float* __restrict__ out, int n)
{
    extern __shared__ float sh[];           // TILE * SH_K floats
    const int base = blockIdx.x * TILE;
    const int t = threadIdx.x;
    const int lane = t & 31;                // point within tile
    const int w = t >> 5;                   // m residue (0..3)
    const int p = base + lane;

    if (p < n) {
        const float x = coords[3 * p + 0];
        const float y = coords[3 * p + 1];
        const float z = coords[3 * p + 2];

        const float r = sqrtf(x * x + y * y + z * z);
        float ct = z / r;
        ct = fminf(1.0f, fmaxf(-1.0f, ct));
        const float st = sqrtf(fmaxf(1.0f - ct * ct, 0.0f));
        const float st2 = st * st;
        const float st4 = st2 * st2;

        const float rho2 = x * x + y * y;
        float c1, s1;
        if (rho2 > 0.0f) {
            const float ir = rsqrtf(rho2);
            c1 = x * ir;
            s1 = y * ir;
        } else {
            c1 = 1.0f;
            s1 = 0.0f;
        }
        const float c2 = fmaf(c1, c1, -(s1 * s1));
        const float s2 = 2.0f * c1 * s1;
        const float c3 = fmaf(c2, c1, -(s2 * s1));
        const float s3 = fmaf(s2, c1, c2 * s1);
        const float c4 = fmaf(c2, c2, -(s2 * s2));
        const float s4 = 2.0f * c2 * s2;

        float* row = sh + lane * SH_K;

        if (w == 0) {
            mchain<0>(row, ct, st4, c4, s4, 1.0f, 1.0f, 0.0f);
        } else if (w == 1) {
            mchain<1>(row, ct, st4, c4, s4, -st, c1, s1);
        } else if (w == 2) {
            const float pmm = (3.0f * st) * st;                 // P_2^2
            mchain<2>(row, ct, st4, c4, s4, pmm, c2, s2);
        } else {
            const float pmm = ((-15.0f * st) * st) * st;        // P_3^3
            mchain<3>(row, ct, st4, c4, s4, pmm, c3, s3);
        }
    }

    // make STS visible to the async proxy, then sync the tile
    asm volatile("fence.proxy.async.shared::cta;" ::: "memory");
    __syncthreads();

    const int npts = min(TILE, n - base);
    if (npts <= 0) return;
    float* gbase = out + (size_t)base * SH_K;

    if (npts == TILE) {
        // full tile: single bulk TMA store (56448 B, 16B-aligned both sides)
        if (t == 0) {
            const uint32_t saddr = smem_u32(sh);
            asm volatile(
                "cp.async.bulk.global.shared::cta.bulk_group [%0], [%1], %2;"
                :: "l"(gbase), "r"(saddr), "r"((uint32_t)SMEM_BYTES)
                : "memory");
            asm volatile("cp.async.bulk.commit_group;" ::: "memory");
            asm volatile("cp.async.bulk.wait_group 0;" ::: "memory");
        }
    } else {
        // partial tail tile: scalar coalesced fallback
        const int total = npts * SH_K;
        for (int i = t; i < total; i += THREADS) {
            gbase[i] = sh[i];
        }
    }
}

extern "C" void kernel_launch(void* const* d_in, const int* in_sizes, int n_in,
                              void* d_out, int out_size) {
    const float* coords = (const float*)d_in[0];
    float* out = (float*)d_out;
    const int n = in_sizes[0] / 3;

    cudaFuncSetAttribute(sph_harm_kernel,
                         cudaFuncAttributeMaxDynamicSharedMemorySize, SMEM_BYTES);
    cudaFuncSetAttribute(sph_harm_kernel,
                         cudaFuncAttributePreferredSharedMemoryCarveout, 100);

    const int blocks = (n + TILE - 1) / TILE;
    sph_harm_kernel<<<blocks, THREADS, SMEM_BYTES>>>(coords, out, n);
}